// round 3
// baseline (speedup 1.0000x reference)
#include <cuda_runtime.h>
#include <math.h>

#define NPTS   8192
#define NB     4
#define NPOINT 409
#define NQ     (NB*NPOINT)   // 1636

// ---------------- device scratch (no allocations allowed) ----------------
__device__ double g_rep_sum;
__device__ double g_uni_sum[5];
__device__ float  g_newxyz[NQ*3];
__device__ int    g_fps_idx[NQ];

// Exact (non-FMA-contracted) squared distance, matching XLA's sub->mul->add.
__device__ __forceinline__ float sqdist3(float ax,float ay,float az,
                                         float bx,float by,float bz){
    float dx=__fsub_rn(ax,bx), dy=__fsub_rn(ay,by), dz=__fsub_rn(az,bz);
    return __fadd_rn(__fadd_rn(__fmul_rn(dx,dx),__fmul_rn(dy,dy)),__fmul_rn(dz,dz));
}

__global__ void init_kernel(){
    if (threadIdx.x==0) g_rep_sum=0.0;
    if (threadIdx.x<5)  g_uni_sum[threadIdx.x]=0.0;
}

// =====================================================================
// Fused kernel: blocks 0..3 run FPS (one per batch), blocks 4..131 run
// the repulsion loss (brute-force ballquery r=0.07, nsample=20).
// =====================================================================
#define FPS_T   256
#define FPS_PPT 32      // 8192 / 256
#define TILE    2048

__global__ __launch_bounds__(256,1) void fps_rep_kernel(const float* __restrict__ pcd){
    __shared__ float4 s_tile[TILE];              // repulsion role
    __shared__ unsigned long long s_wbest[8];    // fps role
    __shared__ float s_cur[3];
    __shared__ float s_red[8];
    const int tid = threadIdx.x;

    if (blockIdx.x < NB){
        // ---------------- FPS role ----------------
        const int b = blockIdx.x;
        const float* __restrict__ P = pcd + b*NPTS*3;
        float x[FPS_PPT], y[FPS_PPT], z[FPS_PPT], dmin[FPS_PPT];
        #pragma unroll
        for (int k=0;k<FPS_PPT;k++){
            int j = tid + k*FPS_T;
            x[k]=P[3*j]; y[k]=P[3*j+1]; z[k]=P[3*j+2];
            dmin[k]=1e10f;
        }
        if (tid==0){ s_cur[0]=P[0]; s_cur[1]=P[1]; s_cur[2]=P[2]; }
        __syncthreads();
        int far = 0;
        for (int t=0;t<NPOINT;t++){
            float px=s_cur[0], py=s_cur[1], pz=s_cur[2];
            if (tid==0){
                int qi = b*NPOINT + t;
                g_fps_idx[qi] = far;
                g_newxyz[3*qi]=px; g_newxyz[3*qi+1]=py; g_newxyz[3*qi+2]=pz;
            }
            float bv = -1.0f; int bj = 0;
            #pragma unroll
            for (int k=0;k<FPS_PPT;k++){
                float d  = sqdist3(x[k],y[k],z[k],px,py,pz);
                float nd = fminf(dmin[k], d);
                dmin[k]  = nd;
                if (nd > bv){ bv = nd; bj = tid + k*FPS_T; }  // strict > keeps lowest j in-thread
            }
            // pack value|inverted-index so u64 max == (max val, min idx) like jnp.argmax
            unsigned long long pk =
                (((unsigned long long)__float_as_uint(bv))<<32) | (unsigned int)(NPTS-1-bj);
            #pragma unroll
            for (int o=16;o;o>>=1){
                unsigned long long q = __shfl_down_sync(0xffffffffu, pk, o);
                pk = (q>pk)? q : pk;
            }
            if ((tid&31)==0) s_wbest[tid>>5] = pk;
            __syncthreads();
            if (tid==0){
                unsigned long long m = s_wbest[0];
                #pragma unroll
                for (int w=1;w<8;w++){ unsigned long long q=s_wbest[w]; m=(q>m)?q:m; }
                int j = (NPTS-1) - (int)(m & 0xffffffffull);
                far = j;
                s_cur[0]=P[3*j]; s_cur[1]=P[3*j+1]; s_cur[2]=P[3*j+2];
            }
            __syncthreads();
        }
    } else {
        // ---------------- repulsion role ----------------
        const int rb = blockIdx.x - NB;        // 0..127, 32 blocks per batch
        const int b  = rb >> 5;
        const int i  = ((rb & 31) << 8) + tid; // point index 0..8191
        const float* __restrict__ P = pcd + b*NPTS*3;
        const float qx=P[3*i], qy=P[3*i+1], qz=P[3*i+2];
        const float R2 = (float)(0.07*0.07);
        float best[5] = {3.4e38f,3.4e38f,3.4e38f,3.4e38f,3.4e38f};
        float h0 = 0.f; int cnt = 0;

        for (int base=0; base<NPTS; base+=TILE){
            for (int j=tid; j<TILE; j+=256){
                int g = base + j;
                s_tile[j] = make_float4(P[3*g],P[3*g+1],P[3*g+2],0.f);
            }
            __syncthreads();
            for (int j=0;j<TILE;j++){
                float4 tp = s_tile[j];
                float dd = sqdist3(qx,qy,qz,tp.x,tp.y,tp.z);
                if (dd<=R2 && cnt<20){          // first 20 hits in ascending index order
                    if (cnt==0) h0 = dd;
                    cnt++;
                    if (dd < best[4]){
                        best[4]=dd;
                        #pragma unroll
                        for (int k=3;k>=0;k--){
                            if (best[k+1]<best[k]){ float tm=best[k]; best[k]=best[k+1]; best[k+1]=tm; }
                        }
                    }
                }
            }
            __syncthreads();
        }
        // ballquery pads missing slots with the first hit (self-distance to first hit)
        for (int t=cnt; t<20; t++){
            if (!(h0 < best[4])) break;
            best[4]=h0;
            #pragma unroll
            for (int k=3;k>=0;k--){
                if (best[k+1]<best[k]){ float tm=best[k]; best[k]=best[k+1]; best[k+1]=tm; }
            }
        }
        const float H2 = (float)(0.03*0.03);
        float s = 0.f;
        #pragma unroll
        for (int k=1;k<5;k++){                   // drop smallest (self), keep next 4
            float d5 = fmaxf(best[k], 0.f);
            float ds = sqrtf(d5);
            float w  = expf((-d5)/H2);
            s = __fadd_rn(s, __fsub_rn(0.07f, __fmul_rn(ds,w)));
        }
        #pragma unroll
        for (int o=16;o;o>>=1) s += __shfl_down_sync(0xffffffffu, s, o);
        if ((tid&31)==0) s_red[tid>>5] = s;
        __syncthreads();
        if (tid==0){
            float tt=0.f;
            #pragma unroll
            for (int w=0;w<8;w++) tt += s_red[w];
            atomicAdd(&g_rep_sum, (double)tt);
        }
    }
}

// =====================================================================
// Uniform loss: one block per (batch, fps-query) per percentage.
// Phase 1: ascending-index ballquery via per-thread contiguous chunks +
// block prefix sum (exact first-nsample semantics with first-hit pad).
// Phase 2: in-group 2nd-smallest pairwise sq-dist per row.
// =====================================================================
__global__ __launch_bounds__(128) void uni_kernel(const float* __restrict__ pcd,
                                                  int nsample, float r2,
                                                  float expectf, float denomf, int slot){
    __shared__ int    s_hidx[131];
    __shared__ int    s_wtot[4];
    __shared__ float4 s_g[131];
    __shared__ float  s_wsum[4];
    const int tid=threadIdx.x, lane=tid&31, wid=tid>>5;
    const int qi = blockIdx.x;
    const int b  = qi / NPOINT;
    const float* __restrict__ P = pcd + b*NPTS*3;
    const float qx=g_newxyz[3*qi], qy=g_newxyz[3*qi+1], qz=g_newxyz[3*qi+2];
    const int beg = tid*64;                       // contiguous chunk -> global ascending order

    int c=0;
    for (int j=beg; j<beg+64; j++){
        float dd = sqdist3(P[3*j],P[3*j+1],P[3*j+2],qx,qy,qz);
        c += (dd<=r2);
    }
    int v=c;
    #pragma unroll
    for (int o=1;o<32;o<<=1){ int u=__shfl_up_sync(0xffffffffu,v,o); if (lane>=o) v+=u; }
    if (lane==31) s_wtot[wid]=v;
    __syncthreads();
    int off=0;
    #pragma unroll
    for (int w=0;w<4;w++) off += (w<wid)? s_wtot[w] : 0;
    const int base  = off + v - c;                // exclusive prefix
    const int total = s_wtot[0]+s_wtot[1]+s_wtot[2]+s_wtot[3];
    const int K     = min(total, nsample);
    if (c>0 && base<nsample){
        int o2 = base;
        for (int j=beg; j<beg+64; j++){
            float dd = sqdist3(P[3*j],P[3*j+1],P[3*j+2],qx,qy,qz);
            if (dd<=r2){ if (o2<nsample) s_hidx[o2]=j; o2++; }
        }
    }
    __syncthreads();
    const int h0 = s_hidx[0];                     // first hit (always exists: query in pcd)
    for (int k=tid; k<nsample; k+=128){
        int j = (k<K)? s_hidx[k] : h0;            // pad with first hit
        s_g[k] = make_float4(P[3*j],P[3*j+1],P[3*j+2],0.f);
    }
    __syncthreads();
    float s=0.f;
    for (int k=tid; k<nsample; k+=128){
        const float ax=s_g[k].x, ay=s_g[k].y, az=s_g[k].z;
        float m1=3.4e38f, m2=3.4e38f;             // two smallest with multiplicity (top_k(-d,2))
        for (int l=0;l<nsample;l++){
            float4 tp = s_g[l];
            float dd = sqdist3(ax,ay,az,tp.x,tp.y,tp.z);
            if (dd<m1){ m2=m1; m1=dd; }
            else if (dd<m2){ m2=dd; }
        }
        float rud = sqrtf(fabsf(__fadd_rn(m2,1e-8f)));
        float dv  = __fsub_rn(rud, expectf);
        s = __fadd_rn(s, __fmul_rn(dv,dv)/denomf);
    }
    #pragma unroll
    for (int o=16;o;o>>=1) s += __shfl_down_sync(0xffffffffu, s, o);
    if (lane==0) s_wsum[wid]=s;
    __syncthreads();
    if (tid==0){
        float tt = s_wsum[0]+s_wsum[1]+s_wsum[2]+s_wsum[3];
        atomicAdd(&g_uni_sum[slot], (double)tt);
    }
}

__global__ void fin_kernel(float* out){
    const double pv[5]  = {0.004,0.008,0.01,0.012,0.016};
    const int    nss[5] = {32,65,81,98,131};
    double u = 0.0;
    for (int i=0;i<5;i++){
        double m = g_uni_sum[i] / ((double)NQ * (double)nss[i]);  // mean over [B*npoint, nsample]
        double w = (pv[i]*100.0)*(pv[i]*100.0);
        u += m*w;
    }
    u /= 5.0;
    out[0] = (float)u;
    out[1] = (float)(g_rep_sum / 131072.0);       // mean over B*N*4
}

extern "C" void kernel_launch(void* const* d_in, const int* in_sizes, int n_in,
                              void* d_out, int out_size){
    (void)in_sizes; (void)n_in; (void)out_size;
    const float* pcd = (const float*)d_in[0];
    float* out = (float*)d_out;

    init_kernel<<<1,32>>>();
    fps_rep_kernel<<<NB + NB*32, 256>>>(pcd);     // 4 FPS blocks + 128 repulsion blocks

    const double ps[5]  = {0.004,0.008,0.01,0.012,0.016};
    const int    nss[5] = {32,65,81,98,131};      // int(8192 * p)
    for (int i=0;i<5;i++){
        double r  = sqrt(ps[i]*1.0);
        float  r2 = (float)(r*r);                                  // radius*radius as in JAX
        double disk = 3.14159265358979323846 * 1.0 * ps[i] / (double)nss[i];
        double el   = sqrt(2.0*disk/1.732);
        uni_kernel<<<NQ,128>>>(pcd, nss[i], r2, (float)el, (float)(el+1e-8), i);
    }
    fin_kernel<<<1,1>>>(out);
}

// round 5
// speedup vs baseline: 3.0632x; 3.0632x over previous
#include <cuda_runtime.h>
#include <math.h>

#define NPTS   8192
#define NB     4
#define NPOINT 409
#define NQ     (NB*NPOINT)   // 1636

// ---------------- device scratch (no allocations allowed) ----------------
__device__ double g_rep_sum;
__device__ double g_uni_sum[5];
__device__ float  g_newxyz[NQ*3];
__device__ int    g_fps_idx[NQ];

// Exact (non-FMA-contracted) squared distance, matching XLA's sub->mul->add.
__device__ __forceinline__ float sqdist3(float ax,float ay,float az,
                                         float bx,float by,float bz){
    float dx=__fsub_rn(ax,bx), dy=__fsub_rn(ay,by), dz=__fsub_rn(az,bz);
    return __fadd_rn(__fadd_rn(__fmul_rn(dx,dx),__fmul_rn(dy,dy)),__fmul_rn(dz,dz));
}

__global__ void init_kernel(){
    if (threadIdx.x==0) g_rep_sum=0.0;
    if (threadIdx.x<5)  g_uni_sum[threadIdx.x]=0.0;
}

// =====================================================================
// Fused kernel: blocks 0..3 run FPS (one per batch), blocks 4..131 run
// the repulsion loss (brute-force ballquery r=0.07, nsample=20).
// (unchanged from passing R2 kernel — numerics are load-bearing)
// =====================================================================
#define FPS_T   256
#define FPS_PPT 32      // 8192 / 256
#define TILE    2048

__global__ __launch_bounds__(256,1) void fps_rep_kernel(const float* __restrict__ pcd){
    __shared__ float4 s_tile[TILE];              // repulsion role
    __shared__ unsigned long long s_wbest[8];    // fps role
    __shared__ float s_cur[3];
    __shared__ float s_red[8];
    const int tid = threadIdx.x;

    if (blockIdx.x < NB){
        // ---------------- FPS role ----------------
        const int b = blockIdx.x;
        const float* __restrict__ P = pcd + b*NPTS*3;
        float x[FPS_PPT], y[FPS_PPT], z[FPS_PPT], dmin[FPS_PPT];
        #pragma unroll
        for (int k=0;k<FPS_PPT;k++){
            int j = tid + k*FPS_T;
            x[k]=P[3*j]; y[k]=P[3*j+1]; z[k]=P[3*j+2];
            dmin[k]=1e10f;
        }
        if (tid==0){ s_cur[0]=P[0]; s_cur[1]=P[1]; s_cur[2]=P[2]; }
        __syncthreads();
        int far = 0;
        for (int t=0;t<NPOINT;t++){
            float px=s_cur[0], py=s_cur[1], pz=s_cur[2];
            if (tid==0){
                int qi = b*NPOINT + t;
                g_fps_idx[qi] = far;
                g_newxyz[3*qi]=px; g_newxyz[3*qi+1]=py; g_newxyz[3*qi+2]=pz;
            }
            float bv = -1.0f; int bj = 0;
            #pragma unroll
            for (int k=0;k<FPS_PPT;k++){
                float d  = sqdist3(x[k],y[k],z[k],px,py,pz);
                float nd = fminf(dmin[k], d);
                dmin[k]  = nd;
                if (nd > bv){ bv = nd; bj = tid + k*FPS_T; }  // strict > keeps lowest j in-thread
            }
            unsigned long long pk =
                (((unsigned long long)__float_as_uint(bv))<<32) | (unsigned int)(NPTS-1-bj);
            #pragma unroll
            for (int o=16;o;o>>=1){
                unsigned long long q = __shfl_down_sync(0xffffffffu, pk, o);
                pk = (q>pk)? q : pk;
            }
            if ((tid&31)==0) s_wbest[tid>>5] = pk;
            __syncthreads();
            if (tid==0){
                unsigned long long m = s_wbest[0];
                #pragma unroll
                for (int w=1;w<8;w++){ unsigned long long q=s_wbest[w]; m=(q>m)?q:m; }
                int j = (NPTS-1) - (int)(m & 0xffffffffull);
                far = j;
                s_cur[0]=P[3*j]; s_cur[1]=P[3*j+1]; s_cur[2]=P[3*j+2];
            }
            __syncthreads();
        }
    } else {
        // ---------------- repulsion role ----------------
        const int rb = blockIdx.x - NB;        // 0..127, 32 blocks per batch
        const int b  = rb >> 5;
        const int i  = ((rb & 31) << 8) + tid; // point index 0..8191
        const float* __restrict__ P = pcd + b*NPTS*3;
        const float qx=P[3*i], qy=P[3*i+1], qz=P[3*i+2];
        const float R2 = (float)(0.07*0.07);
        float best[5] = {3.4e38f,3.4e38f,3.4e38f,3.4e38f,3.4e38f};
        float h0 = 0.f; int cnt = 0;

        for (int base=0; base<NPTS; base+=TILE){
            for (int j=tid; j<TILE; j+=256){
                int g = base + j;
                s_tile[j] = make_float4(P[3*g],P[3*g+1],P[3*g+2],0.f);
            }
            __syncthreads();
            for (int j=0;j<TILE;j++){
                float4 tp = s_tile[j];
                float dd = sqdist3(qx,qy,qz,tp.x,tp.y,tp.z);
                if (dd<=R2 && cnt<20){          // first 20 hits in ascending index order
                    if (cnt==0) h0 = dd;
                    cnt++;
                    if (dd < best[4]){
                        best[4]=dd;
                        #pragma unroll
                        for (int k=3;k>=0;k--){
                            if (best[k+1]<best[k]){ float tm=best[k]; best[k]=best[k+1]; best[k+1]=tm; }
                        }
                    }
                }
            }
            __syncthreads();
        }
        for (int t=cnt; t<20; t++){
            if (!(h0 < best[4])) break;
            best[4]=h0;
            #pragma unroll
            for (int k=3;k>=0;k--){
                if (best[k+1]<best[k]){ float tm=best[k]; best[k]=best[k+1]; best[k+1]=tm; }
            }
        }
        const float H2 = (float)(0.03*0.03);
        float s = 0.f;
        #pragma unroll
        for (int k=1;k<5;k++){
            float d5 = fmaxf(best[k], 0.f);
            float ds = sqrtf(d5);
            float w  = expf((-d5)/H2);
            s = __fadd_rn(s, __fsub_rn(0.07f, __fmul_rn(ds,w)));
        }
        #pragma unroll
        for (int o=16;o;o>>=1) s += __shfl_down_sync(0xffffffffu, s, o);
        if ((tid&31)==0) s_red[tid>>5] = s;
        __syncthreads();
        if (tid==0){
            float tt=0.f;
            #pragma unroll
            for (int w=0;w<8;w++) tt += s_red[w];
            atomicAdd(&g_rep_sum, (double)tt);
        }
    }
}

// =====================================================================
// Fused uniform loss: ONE kernel, ONE coalesced scan per query for all
// 5 percentages. One warp per query. Phase 1: ballot-compacted master
// hit list (ascending index) within r_max. Phase 2 per percentage:
// filter master list by r_i (subsequence, first nsample), K x K 2-NN
// with analytic handling of the (nsample-K) pad rows.
// =====================================================================
#define UCAP 192          // master hit-list capacity (actual hits ~<=25)

__global__ __launch_bounds__(256) void uni_fused_kernel(const float* __restrict__ pcd){
    __shared__ float4        s_pts[8][UCAP];     // {x,y,z,d^2}
    __shared__ unsigned char s_sel[8][136];
    __shared__ float         s_acc[5];
    const int tid = threadIdx.x, lane = tid & 31, w = tid >> 5;
    if (tid < 5) s_acc[tid] = 0.f;
    __syncthreads();

    const int qi = blockIdx.x * 8 + w;
    float wsum[5] = {0.f,0.f,0.f,0.f,0.f};

    // per-percentage constants (double math identical to host/JAX scalars)
    const double pv[5]  = {0.004,0.008,0.01,0.012,0.016};
    const int    nss[5] = {32,65,81,98,131};
    float r2s[5], expf_[5], denf_[5];
    #pragma unroll
    for (int i=0;i<5;i++){
        double r = sqrt(pv[i]*1.0);
        r2s[i] = (float)(r*r);
        double disk = 3.14159265358979323846 * 1.0 * pv[i] / (double)nss[i];
        double el   = sqrt(2.0*disk/1.732);
        expf_[i] = (float)el;
        denf_[i] = (float)(el + 1e-8);
    }
    const float r2max = r2s[4];

    if (qi < NQ){
        const int b = qi / NPOINT;
        const float* __restrict__ P = pcd + b*NPTS*3;
        const float qx=g_newxyz[3*qi], qy=g_newxyz[3*qi+1], qz=g_newxyz[3*qi+2];

        // ---- phase 1: coalesced scan + warp-ballot compaction ----
        int cnt = 0;
        for (int base=0; base<NPTS; base+=32){
            const int j = base + lane;
            const float px=P[3*j], py=P[3*j+1], pz=P[3*j+2];
            const float dd = sqdist3(px,py,pz,qx,qy,qz);
            const bool hit = (dd <= r2max);
            const unsigned msk = __ballot_sync(0xffffffffu, hit);
            if (hit){
                int pos = cnt + __popc(msk & ((1u<<lane)-1u));
                if (pos < UCAP) s_pts[w][pos] = make_float4(px,py,pz,dd);
            }
            cnt += __popc(msk);
        }
        if (cnt > UCAP) cnt = UCAP;
        __syncwarp();

        // ---- phase 2: per percentage ----
        #pragma unroll
        for (int i=0;i<5;i++){
            const int   ns  = nss[i];
            const float r2  = r2s[i];
            // filtered selection (ascending order preserved), first ns
            int K = 0;
            for (int base=0; base<cnt && K<ns; base+=32){
                const int m = base + lane;
                const bool sel = (m < cnt) && (s_pts[w][m].w <= r2);
                const unsigned msk = __ballot_sync(0xffffffffu, sel);
                if (sel){
                    int pos = K + __popc(msk & ((1u<<lane)-1u));
                    if (pos < ns) s_sel[w][pos] = (unsigned char)m;
                }
                K += __popc(msk);
            }
            if (K > ns) K = ns;
            __syncwarp();

            const int Ppad = ns - K;
            float s = 0.f;
            const float4 p0 = s_pts[w][s_sel[w][0]];
            // real rows
            for (int r = lane; r < K; r += 32){
                const float4 a = s_pts[w][s_sel[w][r]];
                float m1 = 3.4e38f, m2 = 3.4e38f;
                for (int bb=0; bb<K; bb++){
                    const float4 pb = s_pts[w][s_sel[w][bb]];
                    const float dd = sqdist3(a.x,a.y,a.z,pb.x,pb.y,pb.z);
                    if (dd < m1){ m2 = m1; m1 = dd; }
                    else if (dd < m2){ m2 = dd; }
                }
                if (Ppad > 0){
                    const float dd = sqdist3(a.x,a.y,a.z,p0.x,p0.y,p0.z);
                    if (dd < m1){ m2 = m1; m1 = dd; } else if (dd < m2){ m2 = dd; }
                    if (Ppad > 1){
                        if (dd < m1){ m2 = m1; m1 = dd; } else if (dd < m2){ m2 = dd; }
                    }
                }
                const float rud = sqrtf(fabsf(__fadd_rn(m2, 1e-8f)));
                const float dv  = __fsub_rn(rud, expf_[i]);
                s = __fadd_rn(s, __fmul_rn(dv,dv)/denf_[i]);
            }
            // pad rows: each is a duplicate of p0 -> second-smallest distance is exactly 0
            if (lane == 0 && Ppad > 0){
                const float rud = sqrtf(fabsf(__fadd_rn(0.f, 1e-8f)));
                const float dv  = __fsub_rn(rud, expf_[i]);
                s = __fadd_rn(s, (float)Ppad * (__fmul_rn(dv,dv)/denf_[i]));
            }
            #pragma unroll
            for (int o=16;o;o>>=1) s += __shfl_down_sync(0xffffffffu, s, o);
            wsum[i] = s;
            __syncwarp();
        }
        if (lane == 0){
            #pragma unroll
            for (int i=0;i<5;i++) atomicAdd(&s_acc[i], wsum[i]);
        }
    }
    __syncthreads();
    if (tid < 5) atomicAdd(&g_uni_sum[tid], (double)s_acc[tid]);
}

__global__ void fin_kernel(float* out){
    const double pv[5]  = {0.004,0.008,0.01,0.012,0.016};
    const int    nss[5] = {32,65,81,98,131};
    double u = 0.0;
    for (int i=0;i<5;i++){
        double m = g_uni_sum[i] / ((double)NQ * (double)nss[i]);
        double wgt = (pv[i]*100.0)*(pv[i]*100.0);
        u += m*wgt;
    }
    u /= 5.0;
    out[0] = (float)u;
    out[1] = (float)(g_rep_sum / 131072.0);       // mean over B*N*4
}

extern "C" void kernel_launch(void* const* d_in, const int* in_sizes, int n_in,
                              void* d_out, int out_size){
    (void)in_sizes; (void)n_in; (void)out_size;
    const float* pcd = (const float*)d_in[0];
    float* out = (float*)d_out;

    init_kernel<<<1,32>>>();
    fps_rep_kernel<<<NB + NB*32, 256>>>(pcd);       // 4 FPS blocks + 128 repulsion blocks
    uni_fused_kernel<<<(NQ + 7)/8, 256>>>(pcd);     // 205 blocks, 1 warp per query, all 5 radii
    fin_kernel<<<1,1>>>(out);
}

// round 8
// speedup vs baseline: 3.1575x; 1.0308x over previous
#include <cuda_runtime.h>
#include <math.h>

#define NPTS   8192
#define NB     4
#define NPOINT 409
#define NQ     (NB*NPOINT)   // 1636
#define UNIBLK ((NQ + 7)/8)  // 205

// ---------------- device scratch (no allocations allowed) ----------------
__device__ double g_rep_sum;
__device__ double g_uni_sum[5];
__device__ float  g_newxyz[NQ*3];
__device__ int    g_fps_idx[NQ];
__device__ unsigned int g_done;

// Exact (non-FMA-contracted) squared distance, matching XLA's sub->mul->add.
__device__ __forceinline__ float sqdist3(float ax,float ay,float az,
                                         float bx,float by,float bz){
    float dx=__fsub_rn(ax,bx), dy=__fsub_rn(ay,by), dz=__fsub_rn(az,bz);
    return __fadd_rn(__fadd_rn(__fmul_rn(dx,dx),__fmul_rn(dy,dy)),__fmul_rn(dz,dz));
}

// ---- packed f32x2 helpers (per-lane rn rounding == scalar rn ops) ----
__device__ __forceinline__ unsigned long long pk2(float lo, float hi){
    unsigned long long r;
    asm("mov.b64 %0, {%1, %2};" : "=l"(r) : "f"(lo), "f"(hi));
    return r;
}
__device__ __forceinline__ void unpk2(unsigned long long v, float& lo, float& hi){
    asm("mov.b64 {%0, %1}, %2;" : "=f"(lo), "=f"(hi) : "l"(v));
}
__device__ __forceinline__ unsigned long long add2(unsigned long long a, unsigned long long b){
    unsigned long long r; asm("add.rn.f32x2 %0, %1, %2;" : "=l"(r) : "l"(a), "l"(b)); return r;
}
__device__ __forceinline__ unsigned long long mul2(unsigned long long a, unsigned long long b){
    unsigned long long r; asm("mul.rn.f32x2 %0, %1, %2;" : "=l"(r) : "l"(a), "l"(b)); return r;
}

__global__ void init_kernel(){
    if (threadIdx.x==0){ g_rep_sum=0.0; g_done=0u; }
    if (threadIdx.x<5)  g_uni_sum[threadIdx.x]=0.0;
}

// =====================================================================
// Fused kernel: blocks 0..3 run FPS (one per batch), blocks 4..131 run
// the repulsion loss (brute-force ballquery r=0.07, nsample=20).
// FPS uses packed f32x2 distance math + single-barrier iterations.
// =====================================================================
#define FPS_T   256
#define TILE    2048

__global__ __launch_bounds__(256,1) void fps_rep_kernel(const float* __restrict__ pcd){
    __shared__ float4 s_tile[TILE];                 // repulsion role
    __shared__ unsigned long long s_wbest[2][8];    // fps role (parity double-buffer)
    __shared__ float s_red[8];
    const int tid = threadIdx.x;

    if (blockIdx.x < NB){
        // ---------------- FPS role ----------------
        const int b = blockIdx.x;
        const float* __restrict__ P = pcd + b*NPTS*3;
        // negated coords of 2 points packed per u64: pair m = points
        // j0 = tid + (2m)*256, j1 = tid + (2m+1)*256  (ascending j within thread)
        unsigned long long nx[16], ny[16], nz[16];
        float dmin[32];
        #pragma unroll
        for (int m=0;m<16;m++){
            const int j0 = tid + (2*m  )*FPS_T;
            const int j1 = tid + (2*m+1)*FPS_T;
            nx[m] = pk2(-P[3*j0  ], -P[3*j1  ]);
            ny[m] = pk2(-P[3*j0+1], -P[3*j1+1]);
            nz[m] = pk2(-P[3*j0+2], -P[3*j1+2]);
        }
        #pragma unroll
        for (int k=0;k<32;k++) dmin[k]=1e10f;

        float px=P[0], py=P[1], pz=P[2];
        int far = 0;
        for (int t=0;t<NPOINT;t++){
            if (tid==0){
                const int qi = b*NPOINT + t;
                g_fps_idx[qi] = far;
                g_newxyz[3*qi]=px; g_newxyz[3*qi+1]=py; g_newxyz[3*qi+2]=pz;
            }
            const unsigned long long px2=pk2(px,px), py2=pk2(py,py), pz2=pk2(pz,pz);
            // dual-chain argmax tracker (halves the serial pred chain)
            float bv0=-1.f, bv1=-1.f; int bj0=0, bj1=0;
            #pragma unroll
            for (int m=0;m<16;m++){
                // (px - x) computed as px + (-x): IEEE-identical to __fsub_rn
                const unsigned long long dx=add2(px2,nx[m]);
                const unsigned long long dy=add2(py2,ny[m]);
                const unsigned long long dz=add2(pz2,nz[m]);
                const unsigned long long s2=add2(add2(mul2(dx,dx),mul2(dy,dy)),mul2(dz,dz));
                float d0,d1; unpk2(s2,d0,d1);
                const float n0=fminf(dmin[2*m  ],d0); dmin[2*m  ]=n0;
                const float n1=fminf(dmin[2*m+1],d1); dmin[2*m+1]=n1;
                if (n0>bv0){ bv0=n0; bj0=tid+(2*m  )*FPS_T; }   // strict > keeps lowest j per chain
                if (n1>bv1){ bv1=n1; bj1=tid+(2*m+1)*FPS_T; }
            }
            // merge chains: max value, ties -> smaller index (exact first-index argmax)
            float bv = bv0; int bj = bj0;
            if (bv1>bv0 || (bv1==bv0 && bj1<bj0)){ bv=bv1; bj=bj1; }
            // pack value|inverted-index so u64 max == (max val, min idx) like jnp.argmax
            unsigned long long pk =
                (((unsigned long long)__float_as_uint(bv))<<32) | (unsigned int)(NPTS-1-bj);
            #pragma unroll
            for (int o=16;o;o>>=1){
                const unsigned long long q = __shfl_down_sync(0xffffffffu, pk, o);
                if (q>pk) pk=q;
            }
            if ((tid&31)==0) s_wbest[t&1][tid>>5] = pk;
            __syncthreads();                      // single barrier per iteration
            unsigned long long m0 = s_wbest[t&1][0];
            #pragma unroll
            for (int w=1;w<8;w++){ const unsigned long long q=s_wbest[t&1][w]; if(q>m0)m0=q; }
            const int j = (NPTS-1) - (int)(m0 & 0xffffffffull);
            far = j;
            px=P[3*j]; py=P[3*j+1]; pz=P[3*j+2];  // uniform-address broadcast load (L1-hit)
        }
    } else {
        // ---------------- repulsion role (unchanged, proven numerics) ----------------
        const int rb = blockIdx.x - NB;        // 0..127, 32 blocks per batch
        const int b  = rb >> 5;
        const int i  = ((rb & 31) << 8) + tid; // point index 0..8191
        const float* __restrict__ P = pcd + b*NPTS*3;
        const float qx=P[3*i], qy=P[3*i+1], qz=P[3*i+2];
        const float R2 = (float)(0.07*0.07);
        float best[5] = {3.4e38f,3.4e38f,3.4e38f,3.4e38f,3.4e38f};
        float h0 = 0.f; int cnt = 0;

        for (int base=0; base<NPTS; base+=TILE){
            for (int j=tid; j<TILE; j+=256){
                const int g = base + j;
                s_tile[j] = make_float4(P[3*g],P[3*g+1],P[3*g+2],0.f);
            }
            __syncthreads();
            for (int j=0;j<TILE;j++){
                const float4 tp = s_tile[j];
                const float dd = sqdist3(qx,qy,qz,tp.x,tp.y,tp.z);
                if (dd<=R2 && cnt<20){          // first 20 hits in ascending index order
                    if (cnt==0) h0 = dd;
                    cnt++;
                    if (dd < best[4]){
                        best[4]=dd;
                        #pragma unroll
                        for (int k=3;k>=0;k--){
                            if (best[k+1]<best[k]){ float tm=best[k]; best[k]=best[k+1]; best[k+1]=tm; }
                        }
                    }
                }
            }
            __syncthreads();
        }
        for (int t=cnt; t<20; t++){
            if (!(h0 < best[4])) break;
            best[4]=h0;
            #pragma unroll
            for (int k=3;k>=0;k--){
                if (best[k+1]<best[k]){ float tm=best[k]; best[k]=best[k+1]; best[k+1]=tm; }
            }
        }
        const float H2 = (float)(0.03*0.03);
        float s = 0.f;
        #pragma unroll
        for (int k=1;k<5;k++){
            const float d5 = fmaxf(best[k], 0.f);
            const float ds = sqrtf(d5);
            const float w  = expf((-d5)/H2);
            s = __fadd_rn(s, __fsub_rn(0.07f, __fmul_rn(ds,w)));
        }
        #pragma unroll
        for (int o=16;o;o>>=1) s += __shfl_down_sync(0xffffffffu, s, o);
        if ((tid&31)==0) s_red[tid>>5] = s;
        __syncthreads();
        if (tid==0){
            float tt=0.f;
            #pragma unroll
            for (int w=0;w<8;w++) tt += s_red[w];
            atomicAdd(&g_rep_sum, (double)tt);
        }
    }
}

// =====================================================================
// Fused uniform loss (one coalesced scan per query for all 5 radii) +
// in-kernel finalization by the last block (saves the fin launch).
// =====================================================================
#define UCAP 192          // master hit-list capacity (actual hits ~<=25)

__global__ __launch_bounds__(256) void uni_fused_kernel(const float* __restrict__ pcd,
                                                        float* __restrict__ out){
    __shared__ float4        s_pts[8][UCAP];     // {x,y,z,d^2}
    __shared__ unsigned char s_sel[8][136];
    __shared__ float         s_acc[5];
    const int tid = threadIdx.x, lane = tid & 31, w = tid >> 5;
    if (tid < 5) s_acc[tid] = 0.f;
    __syncthreads();

    const int qi = blockIdx.x * 8 + w;
    float wsum[5] = {0.f,0.f,0.f,0.f,0.f};

    // per-percentage constants (double math identical to host/JAX scalars)
    const double pv[5]  = {0.004,0.008,0.01,0.012,0.016};
    const int    nss[5] = {32,65,81,98,131};
    float r2s[5], expf_[5], denf_[5];
    #pragma unroll
    for (int i=0;i<5;i++){
        double r = sqrt(pv[i]*1.0);
        r2s[i] = (float)(r*r);
        double disk = 3.14159265358979323846 * 1.0 * pv[i] / (double)nss[i];
        double el   = sqrt(2.0*disk/1.732);
        expf_[i] = (float)el;
        denf_[i] = (float)(el + 1e-8);
    }
    const float r2max = r2s[4];

    if (qi < NQ){
        const int b = qi / NPOINT;
        const float* __restrict__ P = pcd + b*NPTS*3;
        const float qx=g_newxyz[3*qi], qy=g_newxyz[3*qi+1], qz=g_newxyz[3*qi+2];

        // ---- phase 1: coalesced scan + warp-ballot compaction ----
        int cnt = 0;
        for (int base=0; base<NPTS; base+=32){
            const int j = base + lane;
            const float px=P[3*j], py=P[3*j+1], pz=P[3*j+2];
            const float dd = sqdist3(px,py,pz,qx,qy,qz);
            const bool hit = (dd <= r2max);
            const unsigned msk = __ballot_sync(0xffffffffu, hit);
            if (hit){
                const int pos = cnt + __popc(msk & ((1u<<lane)-1u));
                if (pos < UCAP) s_pts[w][pos] = make_float4(px,py,pz,dd);
            }
            cnt += __popc(msk);
        }
        if (cnt > UCAP) cnt = UCAP;
        __syncwarp();

        // ---- phase 2: per percentage ----
        #pragma unroll
        for (int i=0;i<5;i++){
            const int   ns  = nss[i];
            const float r2  = r2s[i];
            int K = 0;
            for (int base=0; base<cnt && K<ns; base+=32){
                const int m = base + lane;
                const bool sel = (m < cnt) && (s_pts[w][m].w <= r2);
                const unsigned msk = __ballot_sync(0xffffffffu, sel);
                if (sel){
                    const int pos = K + __popc(msk & ((1u<<lane)-1u));
                    if (pos < ns) s_sel[w][pos] = (unsigned char)m;
                }
                K += __popc(msk);
            }
            if (K > ns) K = ns;
            __syncwarp();

            const int Ppad = ns - K;
            float s = 0.f;
            const float4 p0 = s_pts[w][s_sel[w][0]];
            for (int r = lane; r < K; r += 32){
                const float4 a = s_pts[w][s_sel[w][r]];
                float m1 = 3.4e38f, m2 = 3.4e38f;
                for (int bb=0; bb<K; bb++){
                    const float4 pb = s_pts[w][s_sel[w][bb]];
                    const float dd = sqdist3(a.x,a.y,a.z,pb.x,pb.y,pb.z);
                    if (dd < m1){ m2 = m1; m1 = dd; }
                    else if (dd < m2){ m2 = dd; }
                }
                if (Ppad > 0){
                    const float dd = sqdist3(a.x,a.y,a.z,p0.x,p0.y,p0.z);
                    if (dd < m1){ m2 = m1; m1 = dd; } else if (dd < m2){ m2 = dd; }
                    if (Ppad > 1){
                        if (dd < m1){ m2 = m1; m1 = dd; } else if (dd < m2){ m2 = dd; }
                    }
                }
                const float rud = sqrtf(fabsf(__fadd_rn(m2, 1e-8f)));
                const float dv  = __fsub_rn(rud, expf_[i]);
                s = __fadd_rn(s, __fmul_rn(dv,dv)/denf_[i]);
            }
            if (lane == 0 && Ppad > 0){
                const float rud = sqrtf(fabsf(__fadd_rn(0.f, 1e-8f)));
                const float dv  = __fsub_rn(rud, expf_[i]);
                s = __fadd_rn(s, (float)Ppad * (__fmul_rn(dv,dv)/denf_[i]));
            }
            #pragma unroll
            for (int o=16;o;o>>=1) s += __shfl_down_sync(0xffffffffu, s, o);
            wsum[i] = s;
            __syncwarp();
        }
        if (lane == 0){
            #pragma unroll
            for (int i=0;i<5;i++) atomicAdd(&s_acc[i], wsum[i]);
        }
    }
    __syncthreads();
    if (tid < 5) atomicAdd(&g_uni_sum[tid], (double)s_acc[tid]);
    __syncthreads();

    // ---- finalization by the last block to finish (threadFenceReduction pattern) ----
    if (tid == 0){
        __threadfence();
        const unsigned v = atomicAdd(&g_done, 1u);
        if (v == (unsigned)(UNIBLK - 1)){
            const double pvf[5]  = {0.004,0.008,0.01,0.012,0.016};
            const int    nssf[5] = {32,65,81,98,131};
            double u = 0.0;
            for (int i=0;i<5;i++){
                const double m = g_uni_sum[i] / ((double)NQ * (double)nssf[i]);
                const double wgt = (pvf[i]*100.0)*(pvf[i]*100.0);
                u += m*wgt;
            }
            u /= 5.0;
            out[0] = (float)u;
            out[1] = (float)(g_rep_sum / 131072.0);   // mean over B*N*4
        }
    }
}

extern "C" void kernel_launch(void* const* d_in, const int* in_sizes, int n_in,
                              void* d_out, int out_size){
    (void)in_sizes; (void)n_in; (void)out_size;
    const float* pcd = (const float*)d_in[0];
    float* out = (float*)d_out;

    init_kernel<<<1,32>>>();
    fps_rep_kernel<<<NB + NB*32, 256>>>(pcd);       // 4 FPS blocks + 128 repulsion blocks
    uni_fused_kernel<<<UNIBLK, 256>>>(pcd, out);    // 205 blocks; last one finalizes
}